// round 9
// baseline (speedup 1.0000x reference)
#include <cuda_runtime.h>
#include <cuda_bf16.h>
#include <cstdint>

#define NN 50000
#define EE 600000
#define NPART 196   // ceil(NN/256)

// ---------------- device scratch ----------------
__device__ __align__(16) float g_AB[NN * 128];
__device__ __align__(16) float g_deg[NN];
__device__ __align__(16) float g_dinv[NN];
__device__ __align__(16) float g_xl[NN * 128];
__device__ __align__(16) float g_x1[NN * 128];
__device__ __align__(16) int   g_src[EE];
__device__ __align__(16) int   g_dst[EE];
__device__ __align__(16) int   g_cnt[NN];
__device__ __align__(16) int   g_part[256];
__device__ __align__(16) int   g_row[NN + 1];
__device__ __align__(16) int   g_cur[NN];
__device__ __align__(16) int   g_csrc[EE];
__device__ __align__(16) float g_cw[EE];
// bf16 hi/lo weights, row-major packed bf16x2: [mat][n*64 + colpair]
__device__ __align__(16) unsigned g_Bhi[3][8192];
__device__ __align__(16) unsigned g_Blo[3][8192];

// ---------------- mma.sync helper (base PTX, works on sm_103) ----------------
__device__ __forceinline__ void mma_bf16(float* c, const unsigned* a,
                                         unsigned b0, unsigned b1) {
    asm volatile(
        "mma.sync.aligned.m16n8k16.row.col.f32.bf16.bf16.f32 "
        "{%0,%1,%2,%3}, {%4,%5,%6,%7}, {%8,%9}, {%0,%1,%2,%3};"
        : "+f"(c[0]), "+f"(c[1]), "+f"(c[2]), "+f"(c[3])
        : "r"(a[0]), "r"(a[1]), "r"(a[2]), "r"(a[3]), "r"(b0), "r"(b1));
}

// ---------------- init: zero cnt, deg=1 ----------------
__global__ void init_misc() {
    int i = blockIdx.x * 256 + threadIdx.x;
    if (i < NN) { g_cnt[i] = 0; g_deg[i] = 1.0f; }
}

// ---------------- weight prep: split bf16, row-major pairs ----------------
__global__ void prep_w(const float* __restrict__ Wp1,
                       const float* __restrict__ W1,
                       const float* __restrict__ W2) {
    int idx = blockIdx.x * 256 + threadIdx.x;   // 3*8192 bf16x2 pairs
    if (idx >= 3 * 8192) return;
    int m  = idx >> 13;
    int p  = idx & 8191;
    int n  = p >> 6;       // output channel 0..127
    int k  = (p & 63) * 2;
    float f0, f1;
    if (m == 0) {
        f0 = (n < 64) ? Wp1[n * 256 + k]     : Wp1[(n - 64) * 256 + 128 + k];
        f1 = (n < 64) ? Wp1[n * 256 + k + 1] : Wp1[(n - 64) * 256 + 128 + k + 1];
    } else if (m == 1) { f0 = W1[n * 128 + k]; f1 = W1[n * 128 + k + 1]; }
    else               { f0 = W2[n * 128 + k]; f1 = W2[n * 128 + k + 1]; }
    __nv_bfloat162 h = __floats2bfloat162_rn(f0, f1);
    __nv_bfloat162 l = __floats2bfloat162_rn(f0 - __bfloat162float(h.x),
                                             f1 - __bfloat162float(h.y));
    g_Bhi[m][p] = *(unsigned*)&h;
    g_Blo[m][p] = *(unsigned*)&l;
}

// ---------------- split-bf16 HMMA GEMM: Y[M,128] = X[M,128] @ B^T -------------
// smem layout: 4 buffers [128 rows x 68 words] (stride 68 => conflict-free frags)
#define RS 68
__global__ void __launch_bounds__(256, 1)
gemm_mma(const float* __restrict__ X, const unsigned* __restrict__ Bhi,
         const unsigned* __restrict__ Blo, float* __restrict__ Y, int M) {
    extern __shared__ unsigned sm[];
    unsigned* Ah = sm;
    unsigned* Al = sm + 128 * RS;
    unsigned* Bh = sm + 2 * 128 * RS;
    unsigned* Bl = sm + 3 * 128 * RS;
    const int tid  = threadIdx.x;
    const int lane = tid & 31;
    const int warp = tid >> 5;
    const int wm = warp & 3;     // 4 m-groups of 32 rows
    const int wn = warp >> 2;    // 2 n-groups of 64 cols
    const int g  = lane >> 2;
    const int tg = lane & 3;

    // stage weights (hi+lo) into padded smem
    #pragma unroll 4
    for (int i = tid; i < 8192; i += 256) {
        int n = i >> 6, cp = i & 63;
        Bh[n * RS + cp] = Bhi[i];
        Bl[n * RS + cp] = Blo[i];
    }

    const int ntiles = (M + 127) >> 7;
    for (int tile = blockIdx.x; tile < ntiles; tile += gridDim.x) {
        const int row0 = tile << 7;
        __syncthreads();   // prev tile mma done (A reusable); B ready on 1st iter
        // convert X tile -> bf16 hi/lo pairs in smem
        #pragma unroll 4
        for (int i = tid; i < 8192; i += 256) {
            int r = i >> 6, cp = i & 63;
            int gr = row0 + r;
            float2 f = (gr < M) ? *(const float2*)&X[(size_t)gr * 128 + cp * 2]
                                : make_float2(0.f, 0.f);
            __nv_bfloat162 h = __floats2bfloat162_rn(f.x, f.y);
            __nv_bfloat162 l = __floats2bfloat162_rn(f.x - __bfloat162float(h.x),
                                                     f.y - __bfloat162float(h.y));
            Ah[r * RS + cp] = *(unsigned*)&h;
            Al[r * RS + cp] = *(unsigned*)&l;
        }
        __syncthreads();

        float acc[2][8][4];
        #pragma unroll
        for (int mt = 0; mt < 2; mt++)
            #pragma unroll
            for (int nt = 0; nt < 8; nt++)
                #pragma unroll
                for (int q = 0; q < 4; q++) acc[mt][nt][q] = 0.f;

        #pragma unroll
        for (int kc = 0; kc < 8; kc++) {
            unsigned ah[2][4], al[2][4];
            #pragma unroll
            for (int mt = 0; mt < 2; mt++) {
                int w0 = (wm * 32 + mt * 16 + g) * RS + kc * 8 + tg;
                ah[mt][0] = Ah[w0];
                ah[mt][1] = Ah[w0 + 8 * RS];
                ah[mt][2] = Ah[w0 + 4];
                ah[mt][3] = Ah[w0 + 8 * RS + 4];
                al[mt][0] = Al[w0];
                al[mt][1] = Al[w0 + 8 * RS];
                al[mt][2] = Al[w0 + 4];
                al[mt][3] = Al[w0 + 8 * RS + 4];
            }
            #pragma unroll
            for (int nt = 0; nt < 8; nt++) {
                int nb = (wn * 64 + nt * 8 + g) * RS + kc * 8 + tg;
                unsigned bh0 = Bh[nb], bh1 = Bh[nb + 4];
                unsigned bl0 = Bl[nb], bl1 = Bl[nb + 4];
                #pragma unroll
                for (int mt = 0; mt < 2; mt++) {
                    mma_bf16(acc[mt][nt], ah[mt], bh0, bh1);   // hi*hi
                    mma_bf16(acc[mt][nt], ah[mt], bl0, bl1);   // hi*lo
                    mma_bf16(acc[mt][nt], al[mt], bh0, bh1);   // lo*hi
                }
            }
        }

        // epilogue: direct register -> gmem
        #pragma unroll
        for (int mt = 0; mt < 2; mt++) {
            int r = row0 + wm * 32 + mt * 16 + g;
            #pragma unroll
            for (int nt = 0; nt < 8; nt++) {
                int c = wn * 64 + nt * 8 + tg * 2;
                if (r < M)
                    *(float2*)&Y[(size_t)r * 128 + c] =
                        make_float2(acc[mt][nt][0], acc[mt][nt][1]);
                if (r + 8 < M)
                    *(float2*)&Y[(size_t)(r + 8) * 128 + c] =
                        make_float2(acc[mt][nt][2], acc[mt][nt][3]);
            }
        }
    }
}

// ---------------- edge conversion (dtype-robust) + dst histogram ----------------
__global__ void convert_edges(const int* __restrict__ raw) {
    bool is64 = true;
    #pragma unroll
    for (int i = 1; i < 128; i += 2)
        if (raw[i] != 0) { is64 = false; break; }
    int e = blockIdx.x * blockDim.x + threadIdx.x;
    if (e >= EE) return;
    int s, d;
    if (is64) { s = raw[2 * e];  d = raw[2 * (EE + e)]; }
    else      { s = raw[e];      d = raw[EE + e]; }
    g_src[e] = s;
    g_dst[e] = d;
    atomicAdd(&g_cnt[d], 1);
}

// ---------------- 3-kernel exclusive scan ----------------
__global__ void scan_part() {
    __shared__ int sm[256];
    int tid = threadIdx.x;
    int i = blockIdx.x * 256 + tid;
    sm[tid] = (i < NN) ? g_cnt[i] : 0;
    __syncthreads();
    for (int o = 128; o; o >>= 1) {
        if (tid < o) sm[tid] += sm[tid + o];
        __syncthreads();
    }
    if (tid == 0) g_part[blockIdx.x] = sm[0];
}

__global__ void scan_tops() {
    __shared__ int sm[256];
    int tid = threadIdx.x;
    int v = (tid < NPART) ? g_part[tid] : 0;
    sm[tid] = v;
    __syncthreads();
    for (int o = 1; o < 256; o <<= 1) {
        int t = sm[tid] + ((tid >= o) ? sm[tid - o] : 0);
        __syncthreads();
        sm[tid] = t;
        __syncthreads();
    }
    if (tid < NPART) g_part[tid] = sm[tid] - v;
}

__global__ void scan_final() {
    __shared__ int sm[256];
    int tid = threadIdx.x;
    int i = blockIdx.x * 256 + tid;
    int v = (i < NN) ? g_cnt[i] : 0;
    sm[tid] = v;
    __syncthreads();
    for (int o = 1; o < 256; o <<= 1) {
        int t = sm[tid] + ((tid >= o) ? sm[tid - o] : 0);
        __syncthreads();
        sm[tid] = t;
        __syncthreads();
    }
    if (i < NN) {
        int excl = sm[tid] - v + g_part[blockIdx.x];
        g_row[i] = excl;
        g_cur[i] = excl;
    }
    if (i == 0) g_row[NN] = EE;
}

// ------- fused edge pass: ew = sigmoid(relu(A[s]+B[d]+b).w2+b2); CSR fill; deg --
__global__ void edge_fused(const float* __restrict__ b_p1,
                           const float* __restrict__ W_p2,
                           const float* __restrict__ b_p2) {
    int e = (blockIdx.x * blockDim.x + threadIdx.x) >> 5;
    int lane = threadIdx.x & 31;
    if (e >= EE) return;
    int s = g_src[e];
    int d = g_dst[e];
    float2 a  = *(const float2*)&g_AB[(size_t)s * 128 + lane * 2];
    float2 b  = *(const float2*)&g_AB[(size_t)d * 128 + 64 + lane * 2];
    float2 bp = *(const float2*)&b_p1[lane * 2];
    float2 w2 = *(const float2*)&W_p2[lane * 2];
    float h0 = fmaxf(a.x + b.x + bp.x, 0.f);
    float h1 = fmaxf(a.y + b.y + bp.y, 0.f);
    float p = h0 * w2.x + h1 * w2.y;
    #pragma unroll
    for (int o = 16; o; o >>= 1) p += __shfl_xor_sync(0xffffffffu, p, o);
    if (lane == 0) {
        float v = 1.f / (1.f + expf(-(p + b_p2[0])));
        int slot = atomicAdd(&g_cur[d], 1);
        g_csrc[slot] = s;
        g_cw[slot]   = v;
        atomicAdd(&g_deg[d], v);
    }
}

__global__ void dinv_kernel() {
    int i = blockIdx.x * blockDim.x + threadIdx.x;
    if (i < NN) g_dinv[i] = rsqrtf(g_deg[i]);
}

__global__ void coef_kernel() {
    int n = blockIdx.x * blockDim.x + threadIdx.x;
    if (n >= NN) return;
    int e0 = g_row[n], e1 = g_row[n + 1];
    float dd = g_dinv[n];
    for (int j = e0; j < e1; j++)
        g_cw[j] *= dd * g_dinv[g_csrc[j]];
}

// ---------------- conv (gather) + relu ----------------
__global__ void conv_relu(const float* __restrict__ bias) {
    int n = blockIdx.x;
    int f = threadIdx.x;
    float di = g_dinv[n];
    float acc = bias[f] + di * di * g_xl[(size_t)n * 128 + f];
    int e0 = g_row[n], e1 = g_row[n + 1];
    for (int j = e0; j < e1; j++) {
        int s = g_csrc[j];
        float c = g_cw[j];
        acc += c * g_xl[(size_t)s * 128 + f];
    }
    g_x1[(size_t)n * 128 + f] = fmaxf(acc, 0.f);
}

// ---------------- conv2 + fused head ----------------
__global__ void conv_head(const float* __restrict__ bias,
                          const float* __restrict__ W_lin,
                          const float* __restrict__ b_lin,
                          float* __restrict__ out) {
    int n = blockIdx.x;
    int f = threadIdx.x;
    float di = g_dinv[n];
    float acc = bias[f] + di * di * g_xl[(size_t)n * 128 + f];
    int e0 = g_row[n], e1 = g_row[n + 1];
    for (int j = e0; j < e1; j++) {
        int s = g_csrc[j];
        float c = g_cw[j];
        acc += c * g_xl[(size_t)s * 128 + f];
    }
    float v = fmaxf(acc, 0.f);
    __shared__ float2 red[128];
    red[f] = make_float2(v * W_lin[f], v * W_lin[128 + f]);
    __syncthreads();
    #pragma unroll
    for (int o = 64; o; o >>= 1) {
        if (f < o) {
            red[f].x += red[f + o].x;
            red[f].y += red[f + o].y;
        }
        __syncthreads();
    }
    if (f == 0) {
        out[2 * n + 0] = 1.f / (1.f + expf(-(red[0].x + b_lin[0])));
        out[2 * n + 1] = 1.f / (1.f + expf(-(red[0].y + b_lin[1])));
    }
}

// ---------------- host ----------------
extern "C" void kernel_launch(void* const* d_in, const int* in_sizes, int n_in,
                              void* d_out, int out_size) {
    const float* x     = (const float*)d_in[0];
    const int*   ei    = (const int*)d_in[1];
    const float* W_p1  = (const float*)d_in[2];
    const float* b_p1  = (const float*)d_in[3];
    const float* W_p2  = (const float*)d_in[4];
    const float* b_p2  = (const float*)d_in[5];
    const float* W1    = (const float*)d_in[6];
    const float* b1    = (const float*)d_in[7];
    const float* W2    = (const float*)d_in[8];
    const float* b2    = (const float*)d_in[9];
    const float* W_lin = (const float*)d_in[10];
    const float* b_lin = (const float*)d_in[11];
    float* out = (float*)d_out;

    void *pAB, *pXL, *pX1, *pBhi, *pBlo;
    cudaGetSymbolAddress(&pAB,  g_AB);
    cudaGetSymbolAddress(&pXL,  g_xl);
    cudaGetSymbolAddress(&pX1,  g_x1);
    cudaGetSymbolAddress(&pBhi, g_Bhi);
    cudaGetSymbolAddress(&pBlo, g_Blo);
    const unsigned* Bhi = (const unsigned*)pBhi;
    const unsigned* Blo = (const unsigned*)pBlo;

    const int MMA_SMEM = 4 * 128 * RS * 4;  // 139264 B
    cudaFuncSetAttribute(gemm_mma, cudaFuncAttributeMaxDynamicSharedMemorySize, MMA_SMEM);

    const int GRID        = 148;
    const int edge_blocks = (EE * 32 + 255) / 256;
    const int e_blocks    = (EE + 255) / 256;
    const int n_blocks    = (NN + 255) / 256;

    init_misc<<<NPART, 256>>>();                                          // 0
    prep_w<<<96, 256>>>(W_p1, W1, W2);                                    // 1
    convert_edges<<<e_blocks, 256>>>(ei);                                 // 2
    gemm_mma<<<GRID, 256, MMA_SMEM>>>(x, Bhi, Blo, (float*)pAB, NN);      // 3 (profiled)
    scan_part<<<NPART, 256>>>();                                          // 4
    scan_tops<<<1, 256>>>();                                              // 5
    scan_final<<<NPART, 256>>>();                                         // 6
    edge_fused<<<edge_blocks, 256>>>(b_p1, W_p2, b_p2);                   // 7
    dinv_kernel<<<n_blocks, 256>>>();                                     // 8
    coef_kernel<<<n_blocks, 256>>>();                                     // 9
    gemm_mma<<<GRID, 256, MMA_SMEM>>>(x, Bhi + 8192, Blo + 8192,
                                      (float*)pXL, NN);                   // 10
    conv_relu<<<NN, 128>>>(b1);                                           // 11
    gemm_mma<<<GRID, 256, MMA_SMEM>>>((const float*)pX1, Bhi + 16384,
                                      Blo + 16384, (float*)pXL, NN);      // 12
    conv_head<<<NN, 128>>>(b2, W_lin, b_lin, out);                        // 13
}

// round 10
// speedup vs baseline: 1.0525x; 1.0525x over previous
#include <cuda_runtime.h>
#include <cuda_bf16.h>
#include <cstdint>

#define NN 50000
#define EE 600000
#define NPART 196   // ceil(NN/256)

// ---------------- device scratch ----------------
__device__ __align__(16) float g_AB[NN * 128];
__device__ __align__(16) float g_deg[NN];
__device__ __align__(16) float g_dinv[NN];
__device__ __align__(16) float g_xl[NN * 128];
__device__ __align__(16) float g_x1[NN * 128];
__device__ __align__(16) int   g_src[EE];
__device__ __align__(16) int   g_dst[EE];
__device__ __align__(16) int   g_cnt[NN];
__device__ __align__(16) int   g_part[256];
__device__ __align__(16) int   g_row[NN + 1];
__device__ __align__(16) int   g_cur[NN];
__device__ __align__(16) int   g_csrc[EE];
__device__ __align__(16) float g_cw[EE];
// bf16 hi/lo weights, row-major packed bf16x2: [mat][n*64 + colpair]
__device__ __align__(16) unsigned g_Bhi[3][8192];
__device__ __align__(16) unsigned g_Blo[3][8192];

// ---------------- mma.sync helper (base PTX, works on sm_103) ----------------
__device__ __forceinline__ void mma_bf16(float* c, const unsigned* a,
                                         unsigned b0, unsigned b1) {
    asm volatile(
        "mma.sync.aligned.m16n8k16.row.col.f32.bf16.bf16.f32 "
        "{%0,%1,%2,%3}, {%4,%5,%6,%7}, {%8,%9}, {%0,%1,%2,%3};"
        : "+f"(c[0]), "+f"(c[1]), "+f"(c[2]), "+f"(c[3])
        : "r"(a[0]), "r"(a[1]), "r"(a[2]), "r"(a[3]), "r"(b0), "r"(b1));
}

// ---------------- init: zero cnt, deg=1 ----------------
__global__ void init_misc() {
    int i = blockIdx.x * 256 + threadIdx.x;
    if (i < NN) { g_cnt[i] = 0; g_deg[i] = 1.0f; }
}

// ---------------- weight prep: split bf16, row-major pairs ----------------
__global__ void prep_w(const float* __restrict__ Wp1,
                       const float* __restrict__ W1,
                       const float* __restrict__ W2) {
    int idx = blockIdx.x * 256 + threadIdx.x;   // 3*8192 bf16x2 pairs
    if (idx >= 3 * 8192) return;
    int m  = idx >> 13;
    int p  = idx & 8191;
    int n  = p >> 6;       // output channel 0..127
    int k  = (p & 63) * 2;
    float f0, f1;
    if (m == 0) {
        f0 = (n < 64) ? Wp1[n * 256 + k]     : Wp1[(n - 64) * 256 + 128 + k];
        f1 = (n < 64) ? Wp1[n * 256 + k + 1] : Wp1[(n - 64) * 256 + 128 + k + 1];
    } else if (m == 1) { f0 = W1[n * 128 + k]; f1 = W1[n * 128 + k + 1]; }
    else               { f0 = W2[n * 128 + k]; f1 = W2[n * 128 + k + 1]; }
    __nv_bfloat162 h = __floats2bfloat162_rn(f0, f1);
    __nv_bfloat162 l = __floats2bfloat162_rn(f0 - __bfloat162float(h.x),
                                             f1 - __bfloat162float(h.y));
    g_Bhi[m][p] = *(unsigned*)&h;
    g_Blo[m][p] = *(unsigned*)&l;
}

// ---------------- split-bf16 HMMA GEMM: Y[M,128] = X[M,128] @ B^T -------------
// 64-row tiles, 2 CTAs/SM for phase overlap.
// smem: Ah/Al [64 x 68], Bh/Bl [128 x 68] words (stride 68 => conflict-free)
#define RS 68
__global__ void __launch_bounds__(256, 2)
gemm_mma(const float* __restrict__ X, const unsigned* __restrict__ Bhi,
         const unsigned* __restrict__ Blo, float* __restrict__ Y, int M) {
    extern __shared__ unsigned sm[];
    unsigned* Ah = sm;                    //  64*RS
    unsigned* Al = sm + 64 * RS;          //  64*RS
    unsigned* Bh = sm + 128 * RS;         // 128*RS
    unsigned* Bl = sm + 256 * RS;         // 128*RS
    const int tid  = threadIdx.x;
    const int lane = tid & 31;
    const int warp = tid >> 5;
    const int wm = warp & 3;     // 4 m-groups of 16 rows
    const int wn = warp >> 2;    // 2 n-groups of 64 cols
    const int g  = lane >> 2;
    const int tg = lane & 3;

    // stage weights (hi+lo) into padded smem
    #pragma unroll 4
    for (int i = tid; i < 8192; i += 256) {
        int n = i >> 6, cp = i & 63;
        Bh[n * RS + cp] = Bhi[i];
        Bl[n * RS + cp] = Blo[i];
    }

    const int ntiles = (M + 63) >> 6;
    for (int tile = blockIdx.x; tile < ntiles; tile += gridDim.x) {
        const int row0 = tile << 6;
        __syncthreads();   // prev tile MMA done (A reusable); B ready on 1st iter
        // convert X tile (64 rows) -> bf16 hi/lo pairs in smem
        #pragma unroll 4
        for (int i = tid; i < 4096; i += 256) {
            int r = i >> 6, cp = i & 63;
            int gr = row0 + r;
            float2 f = (gr < M) ? *(const float2*)&X[(size_t)gr * 128 + cp * 2]
                                : make_float2(0.f, 0.f);
            __nv_bfloat162 h = __floats2bfloat162_rn(f.x, f.y);
            __nv_bfloat162 l = __floats2bfloat162_rn(f.x - __bfloat162float(h.x),
                                                     f.y - __bfloat162float(h.y));
            Ah[r * RS + cp] = *(unsigned*)&h;
            Al[r * RS + cp] = *(unsigned*)&l;
        }
        __syncthreads();

        float acc[8][4];
        #pragma unroll
        for (int nt = 0; nt < 8; nt++)
            #pragma unroll
            for (int q = 0; q < 4; q++) acc[nt][q] = 0.f;

        #pragma unroll
        for (int kc = 0; kc < 8; kc++) {
            unsigned ah[4], al[4];
            {
                int w0 = (wm * 16 + g) * RS + kc * 8 + tg;
                ah[0] = Ah[w0];
                ah[1] = Ah[w0 + 8 * RS];
                ah[2] = Ah[w0 + 4];
                ah[3] = Ah[w0 + 8 * RS + 4];
                al[0] = Al[w0];
                al[1] = Al[w0 + 8 * RS];
                al[2] = Al[w0 + 4];
                al[3] = Al[w0 + 8 * RS + 4];
            }
            #pragma unroll
            for (int nt = 0; nt < 8; nt++) {
                int nb = (wn * 64 + nt * 8 + g) * RS + kc * 8 + tg;
                unsigned bh0 = Bh[nb], bh1 = Bh[nb + 4];
                unsigned bl0 = Bl[nb], bl1 = Bl[nb + 4];
                mma_bf16(acc[nt], ah, bh0, bh1);   // hi*hi
                mma_bf16(acc[nt], ah, bl0, bl1);   // hi*lo
                mma_bf16(acc[nt], al, bh0, bh1);   // lo*hi
            }
        }

        // epilogue: direct register -> gmem
        int r = row0 + wm * 16 + g;
        #pragma unroll
        for (int nt = 0; nt < 8; nt++) {
            int c = wn * 64 + nt * 8 + tg * 2;
            if (r < M)
                *(float2*)&Y[(size_t)r * 128 + c] =
                    make_float2(acc[nt][0], acc[nt][1]);
            if (r + 8 < M)
                *(float2*)&Y[(size_t)(r + 8) * 128 + c] =
                    make_float2(acc[nt][2], acc[nt][3]);
        }
    }
}

// ---------------- edge conversion (dtype-robust) + dst histogram ----------------
__global__ void convert_edges(const int* __restrict__ raw) {
    bool is64 = true;
    #pragma unroll
    for (int i = 1; i < 128; i += 2)
        if (raw[i] != 0) { is64 = false; break; }
    int e = blockIdx.x * blockDim.x + threadIdx.x;
    if (e >= EE) return;
    int s, d;
    if (is64) { s = raw[2 * e];  d = raw[2 * (EE + e)]; }
    else      { s = raw[e];      d = raw[EE + e]; }
    g_src[e] = s;
    g_dst[e] = d;
    atomicAdd(&g_cnt[d], 1);
}

// ---------------- 3-kernel exclusive scan ----------------
__global__ void scan_part() {
    __shared__ int sm[256];
    int tid = threadIdx.x;
    int i = blockIdx.x * 256 + tid;
    sm[tid] = (i < NN) ? g_cnt[i] : 0;
    __syncthreads();
    for (int o = 128; o; o >>= 1) {
        if (tid < o) sm[tid] += sm[tid + o];
        __syncthreads();
    }
    if (tid == 0) g_part[blockIdx.x] = sm[0];
}

__global__ void scan_tops() {
    __shared__ int sm[256];
    int tid = threadIdx.x;
    int v = (tid < NPART) ? g_part[tid] : 0;
    sm[tid] = v;
    __syncthreads();
    for (int o = 1; o < 256; o <<= 1) {
        int t = sm[tid] + ((tid >= o) ? sm[tid - o] : 0);
        __syncthreads();
        sm[tid] = t;
        __syncthreads();
    }
    if (tid < NPART) g_part[tid] = sm[tid] - v;
}

__global__ void scan_final() {
    __shared__ int sm[256];
    int tid = threadIdx.x;
    int i = blockIdx.x * 256 + tid;
    int v = (i < NN) ? g_cnt[i] : 0;
    sm[tid] = v;
    __syncthreads();
    for (int o = 1; o < 256; o <<= 1) {
        int t = sm[tid] + ((tid >= o) ? sm[tid - o] : 0);
        __syncthreads();
        sm[tid] = t;
        __syncthreads();
    }
    if (i < NN) {
        int excl = sm[tid] - v + g_part[blockIdx.x];
        g_row[i] = excl;
        g_cur[i] = excl;
    }
    if (i == 0) g_row[NN] = EE;
}

// ------- fused edge pass: ew = sigmoid(relu(A[s]+B[d]+b).w2+b2); CSR fill; deg --
__global__ void edge_fused(const float* __restrict__ b_p1,
                           const float* __restrict__ W_p2,
                           const float* __restrict__ b_p2) {
    int e = (blockIdx.x * blockDim.x + threadIdx.x) >> 5;
    int lane = threadIdx.x & 31;
    if (e >= EE) return;
    int s = g_src[e];
    int d = g_dst[e];
    float2 a  = *(const float2*)&g_AB[(size_t)s * 128 + lane * 2];
    float2 b  = *(const float2*)&g_AB[(size_t)d * 128 + 64 + lane * 2];
    float2 bp = *(const float2*)&b_p1[lane * 2];
    float2 w2 = *(const float2*)&W_p2[lane * 2];
    float h0 = fmaxf(a.x + b.x + bp.x, 0.f);
    float h1 = fmaxf(a.y + b.y + bp.y, 0.f);
    float p = h0 * w2.x + h1 * w2.y;
    #pragma unroll
    for (int o = 16; o; o >>= 1) p += __shfl_xor_sync(0xffffffffu, p, o);
    if (lane == 0) {
        float v = 1.f / (1.f + expf(-(p + b_p2[0])));
        int slot = atomicAdd(&g_cur[d], 1);
        g_csrc[slot] = s;
        g_cw[slot]   = v;
        atomicAdd(&g_deg[d], v);
    }
}

__global__ void dinv_kernel() {
    int i = blockIdx.x * blockDim.x + threadIdx.x;
    if (i < NN) g_dinv[i] = rsqrtf(g_deg[i]);
}

__global__ void coef_kernel() {
    int n = blockIdx.x * blockDim.x + threadIdx.x;
    if (n >= NN) return;
    int e0 = g_row[n], e1 = g_row[n + 1];
    float dd = g_dinv[n];
    for (int j = e0; j < e1; j++)
        g_cw[j] *= dd * g_dinv[g_csrc[j]];
}

// ---------------- conv (gather) + relu ----------------
__global__ void conv_relu(const float* __restrict__ bias) {
    int n = blockIdx.x;
    int f = threadIdx.x;
    float di = g_dinv[n];
    float acc = bias[f] + di * di * g_xl[(size_t)n * 128 + f];
    int e0 = g_row[n], e1 = g_row[n + 1];
    for (int j = e0; j < e1; j++) {
        int s = g_csrc[j];
        float c = g_cw[j];
        acc += c * g_xl[(size_t)s * 128 + f];
    }
    g_x1[(size_t)n * 128 + f] = fmaxf(acc, 0.f);
}

// ---------------- conv2 + fused head ----------------
__global__ void conv_head(const float* __restrict__ bias,
                          const float* __restrict__ W_lin,
                          const float* __restrict__ b_lin,
                          float* __restrict__ out) {
    int n = blockIdx.x;
    int f = threadIdx.x;
    float di = g_dinv[n];
    float acc = bias[f] + di * di * g_xl[(size_t)n * 128 + f];
    int e0 = g_row[n], e1 = g_row[n + 1];
    for (int j = e0; j < e1; j++) {
        int s = g_csrc[j];
        float c = g_cw[j];
        acc += c * g_xl[(size_t)s * 128 + f];
    }
    float v = fmaxf(acc, 0.f);
    __shared__ float2 red[128];
    red[f] = make_float2(v * W_lin[f], v * W_lin[128 + f]);
    __syncthreads();
    #pragma unroll
    for (int o = 64; o; o >>= 1) {
        if (f < o) {
            red[f].x += red[f + o].x;
            red[f].y += red[f + o].y;
        }
        __syncthreads();
    }
    if (f == 0) {
        out[2 * n + 0] = 1.f / (1.f + expf(-(red[0].x + b_lin[0])));
        out[2 * n + 1] = 1.f / (1.f + expf(-(red[0].y + b_lin[1])));
    }
}

// ---------------- host ----------------
extern "C" void kernel_launch(void* const* d_in, const int* in_sizes, int n_in,
                              void* d_out, int out_size) {
    const float* x     = (const float*)d_in[0];
    const int*   ei    = (const int*)d_in[1];
    const float* W_p1  = (const float*)d_in[2];
    const float* b_p1  = (const float*)d_in[3];
    const float* W_p2  = (const float*)d_in[4];
    const float* b_p2  = (const float*)d_in[5];
    const float* W1    = (const float*)d_in[6];
    const float* b1    = (const float*)d_in[7];
    const float* W2    = (const float*)d_in[8];
    const float* b2    = (const float*)d_in[9];
    const float* W_lin = (const float*)d_in[10];
    const float* b_lin = (const float*)d_in[11];
    float* out = (float*)d_out;

    void *pAB, *pXL, *pX1, *pBhi, *pBlo;
    cudaGetSymbolAddress(&pAB,  g_AB);
    cudaGetSymbolAddress(&pXL,  g_xl);
    cudaGetSymbolAddress(&pX1,  g_x1);
    cudaGetSymbolAddress(&pBhi, g_Bhi);
    cudaGetSymbolAddress(&pBlo, g_Blo);
    const unsigned* Bhi = (const unsigned*)pBhi;
    const unsigned* Blo = (const unsigned*)pBlo;

    const int MMA_SMEM = 384 * RS * 4;  // 104448 B -> 2 CTAs/SM
    cudaFuncSetAttribute(gemm_mma, cudaFuncAttributeMaxDynamicSharedMemorySize, MMA_SMEM);

    const int GRID        = 296;
    const int edge_blocks = (EE * 32 + 255) / 256;
    const int e_blocks    = (EE + 255) / 256;
    const int n_blocks    = (NN + 255) / 256;

    init_misc<<<NPART, 256>>>();                                          // 0
    prep_w<<<96, 256>>>(W_p1, W1, W2);                                    // 1
    convert_edges<<<e_blocks, 256>>>(ei);                                 // 2
    gemm_mma<<<GRID, 256, MMA_SMEM>>>(x, Bhi, Blo, (float*)pAB, NN);      // 3 (profiled)
    scan_part<<<NPART, 256>>>();                                          // 4
    scan_tops<<<1, 256>>>();                                              // 5
    scan_final<<<NPART, 256>>>();                                         // 6
    edge_fused<<<edge_blocks, 256>>>(b_p1, W_p2, b_p2);                   // 7
    dinv_kernel<<<n_blocks, 256>>>();                                     // 8
    coef_kernel<<<n_blocks, 256>>>();                                     // 9
    gemm_mma<<<GRID, 256, MMA_SMEM>>>(x, Bhi + 8192, Blo + 8192,
                                      (float*)pXL, NN);                   // 10
    conv_relu<<<NN, 128>>>(b1);                                           // 11
    gemm_mma<<<GRID, 256, MMA_SMEM>>>((const float*)pX1, Bhi + 16384,
                                      Blo + 16384, (float*)pXL, NN);      // 12
    conv_head<<<NN, 128>>>(b2, W_lin, b_lin, out);                        // 13
}